// round 5
// baseline (speedup 1.0000x reference)
#include <cuda_runtime.h>

// LIF recurrence: v = alpha*v + beta*c; spike = (v >= 1); v = spike ? 0 : v.
// Sequential over T=2048, parallel over N=32768.
// Output: out[0 : T*N] = spikes, out[T*N : 2*T*N] = post-reset voltages.
//
// HBM-bound (768 MB mandatory). R4 (STAGES=32) measured DRAM=62% with ~28KB/SM
// in flight -> implied loaded DRAM latency ~1000cyc, need ~30KB/SM minimum.
// R5: STAGES=64 (8 commit groups of 8) -> ~56-64KB/SM in flight, 2x margin.

#define T_STEPS 2048
#define N_NEUR  32768
#define BLOCK   128
#define STAGES  64                 // smem pipeline depth (steps)
#define GRP     8                  // steps per cp.async commit group
#define NGRP    (STAGES / GRP)     // 8 groups in flight

__device__ __forceinline__ void cp_async4(unsigned saddr, const float* gptr)
{
    asm volatile("cp.async.ca.shared.global [%0], [%1], 4;"
                 :: "r"(saddr), "l"(gptr));
}
__device__ __forceinline__ void cp_commit()
{
    asm volatile("cp.async.commit_group;");
}
__device__ __forceinline__ void cp_wait_allow()
{
    asm volatile("cp.async.wait_group %0;" :: "n"(NGRP - 1));
}

__global__ void __launch_bounds__(BLOCK, 2)
lif_kernel(const float* __restrict__ cur,
           const float* __restrict__ v0,
           float* __restrict__ out)
{
    __shared__ float sbuf[STAGES * BLOCK];   // 32 KB

    const int tid = threadIdx.x;
    const int n   = blockIdx.x * BLOCK + tid;

    // Match reference f32 constants: alpha = f32(exp(-1/20)), beta = f32(1 - alpha)
    const float alpha = (float)0.9512294245007140;
    const float beta  = (float)(1.0 - 0.9512294245007140);

    float v = v0[n];

    const float* cp = cur + n;
    float* sp = out + n;                                  // spikes
    float* vp = out + (size_t)T_STEPS * N_NEUR + n;       // voltages

    const unsigned sbase =
        (unsigned)__cvta_generic_to_shared(sbuf) + (unsigned)tid * 4u;

    // ---- Prime: issue all STAGES stages as NGRP commit groups ----
#pragma unroll
    for (int g = 0; g < NGRP; ++g) {
#pragma unroll
        for (int i = 0; i < GRP; ++i) {
            const int s = g * GRP + i;
            cp_async4(sbase + (unsigned)(s * BLOCK) * 4u,
                      cp + (size_t)s * N_NEUR);
        }
        cp_commit();
    }
    cp += (size_t)STAGES * N_NEUR;

    // ---- Main loop: one commit group (8 steps) per iteration ----
    for (int t = 0; t < T_STEPS; t += GRP) {
        cp_wait_allow();                       // oldest group (steps t..t+7) ready

        const int slot = (t / GRP) & (NGRP - 1);   // group slot 0..7

        // Read this group's 8 currents from smem first...
        float c[GRP];
#pragma unroll
        for (int i = 0; i < GRP; ++i)
            c[i] = sbuf[(slot * GRP + i) * BLOCK + tid];

        // ...then reuse the slot for steps t+STAGES..t+STAGES+7.
        if (t + STAGES < T_STEPS) {
#pragma unroll
            for (int i = 0; i < GRP; ++i)
                cp_async4(sbase + (unsigned)((slot * GRP + i) * BLOCK) * 4u,
                          cp + (size_t)i * N_NEUR);
            cp += (size_t)GRP * N_NEUR;
        }
        cp_commit();                           // empty group near the tail is fine

        // Compute + store the 8 steps.
#pragma unroll
        for (int i = 0; i < GRP; ++i) {
            // v = alpha*v + beta*c, explicitly unfused to match reference rounding
            v = __fadd_rn(__fmul_rn(alpha, v), __fmul_rn(beta, c[i]));
            const bool fire = (v >= 1.0f);
            const float s = fire ? 1.0f : 0.0f;
            v = fire ? 0.0f : v;
            *sp = s;
            *vp = v;
            sp += N_NEUR;
            vp += N_NEUR;
        }
    }
}

extern "C" void kernel_launch(void* const* d_in, const int* in_sizes, int n_in,
                              void* d_out, int out_size)
{
    const float* currents = (const float*)d_in[0];   // (T, N) float32
    const float* v0       = (const float*)d_in[1];   // (N,)  float32
    float* out            = (float*)d_out;           // 2*T*N float32

    lif_kernel<<<N_NEUR / BLOCK, BLOCK>>>(currents, v0, out);
}